// round 8
// baseline (speedup 1.0000x reference)
#include <cuda_runtime.h>

#define N_NODES 50000
#define N_EDGES 800000
#define IN_DIM 128
#define HID_DIM 256
#define OUT_DIM 5

// ---------------- scratch (device globals; no allocation allowed) -------------
__device__ int   g_cnt [N_NODES];            // in-degree
__device__ int   g_off [N_NODES];            // CSR offsets (exclusive scan)
__device__ int   g_cur [N_NODES];            // fill cursors
__device__ float g_inv [N_NODES];            // 1/max(cnt,1)
__device__ int   g_nbr [N_EDGES];            // CSR: src ids grouped by dst
__device__ float g_agg1[N_NODES * IN_DIM];   // mean of x[src] per dst
__device__ float g_h   [N_NODES * HID_DIM];  // layer-1 output
__device__ float g_p   [N_NODES * 8];        // h @ W2l^T (5 used, padded to 8)
__device__ float g_q   [N_NODES * 8];        // h @ W2r^T (5 used, padded to 8)

// ---------------- CSR build ----------------------------------------------------

__global__ void k_zero_cnt() {
    int i = blockIdx.x * blockDim.x + threadIdx.x;
    if (i < N_NODES) g_cnt[i] = 0;
}

// edge_index is int32: [src[0..E) | dst[0..E)]
__global__ void k_hist(const int* __restrict__ ei) {
    int e = blockIdx.x * blockDim.x + threadIdx.x;
    if (e >= N_EDGES) return;
    atomicAdd(&g_cnt[ei[N_EDGES + e]], 1);
}

// single-block exclusive scan of 50k counts; also writes cursors and 1/deg
__global__ void __launch_bounds__(1024) k_scan() {
    const int PER = (N_NODES + 1023) / 1024;   // 49
    int t = threadIdx.x;
    int beg = t * PER;
    int end = min(beg + PER, N_NODES);

    int s = 0;
    for (int i = beg; i < end; ++i) s += g_cnt[i];

    __shared__ int sh[1024];
    sh[t] = s;
    __syncthreads();
    for (int d = 1; d < 1024; d <<= 1) {
        int v = (t >= d) ? sh[t - d] : 0;
        __syncthreads();
        sh[t] += v;
        __syncthreads();
    }
    int run = (t == 0) ? 0 : sh[t - 1];
    for (int i = beg; i < end; ++i) {
        int c = g_cnt[i];
        g_off[i] = run;
        g_cur[i] = run;
        g_inv[i] = 1.0f / (float)max(c, 1);
        run += c;
    }
}

__global__ void k_fill(const int* __restrict__ ei) {
    int e = blockIdx.x * blockDim.x + threadIdx.x;
    if (e >= N_EDGES) return;
    int src = ei[e];
    int dst = ei[N_EDGES + e];
    int pos = atomicAdd(&g_cur[dst], 1);
    g_nbr[pos] = src;
}

// ---------------- layer-1 aggregation: warp per node, gather-sum ---------------
__global__ void __launch_bounds__(256) k_agg1(const float* __restrict__ x) {
    int node = (blockIdx.x * blockDim.x + threadIdx.x) >> 5;
    int lane = threadIdx.x & 31;
    if (node >= N_NODES) return;

    int off = g_off[node];
    int cnt = g_cnt[node];
    const float4* x4 = reinterpret_cast<const float4*>(x);

    float4 acc = make_float4(0.f, 0.f, 0.f, 0.f);
    int j = 0;
    for (; j + 2 <= cnt; j += 2) {
        int s0 = g_nbr[off + j];
        int s1 = g_nbr[off + j + 1];
        float4 v0 = x4[(size_t)s0 * 32 + lane];
        float4 v1 = x4[(size_t)s1 * 32 + lane];
        acc.x += v0.x + v1.x; acc.y += v0.y + v1.y;
        acc.z += v0.z + v1.z; acc.w += v0.w + v1.w;
    }
    if (j < cnt) {
        float4 v = x4[(size_t)g_nbr[off + j] * 32 + lane];
        acc.x += v.x; acc.y += v.y; acc.z += v.z; acc.w += v.w;
    }
    float inv = g_inv[node];
    acc.x *= inv; acc.y *= inv; acc.z *= inv; acc.w *= inv;
    reinterpret_cast<float4*>(g_agg1)[(size_t)node * 32 + lane] = acc;
}

// ---------------- layer-1 GEMM: h = relu([mean | x] @ [W1l ; W1r]^T + b1l) ------
// M=50000, K=256 (virtual concat), N=256. BM=BN=64, BK=16, 256 thr, 4x4 microtile.
__global__ void __launch_bounds__(256)
k_gemm1(const float* __restrict__ x,  const float* __restrict__ W1l,
        const float* __restrict__ b1l, const float* __restrict__ W1r) {
    __shared__ float As[16][68];
    __shared__ float Bs[16][68];

    int bm = blockIdx.x;
    int bn = blockIdx.y;
    int tid = threadIdx.x;

    int aRow = tid >> 2;            // 0..63
    int aC4  = (tid & 3) * 4;       // 0,4,8,12
    int row  = bm * 64 + aRow;

    int bN   = tid >> 2;
    int bC4  = (tid & 3) * 4;
    int wrow = bn * 64 + bN;        // 0..255 output feature

    int tr = (tid >> 4) * 4;
    int tc = (tid & 15) * 4;

    float acc[4][4] = {};

    for (int kt = 0; kt < 16; ++kt) {
        float4 a = make_float4(0.f, 0.f, 0.f, 0.f);
        int ka = kt * 16 + aC4;
        if (row < N_NODES) {
            if (ka < 128)
                a = *reinterpret_cast<const float4*>(g_agg1 + (size_t)row * 128 + ka);
            else
                a = *reinterpret_cast<const float4*>(x + (size_t)row * 128 + (ka - 128));
        }
        int kb = kt * 16 + bC4;
        float4 b;
        if (kb < 128) b = *reinterpret_cast<const float4*>(W1l + (size_t)wrow * 128 + kb);
        else          b = *reinterpret_cast<const float4*>(W1r + (size_t)wrow * 128 + (kb - 128));

        __syncthreads();
        As[aC4 + 0][aRow] = a.x; As[aC4 + 1][aRow] = a.y;
        As[aC4 + 2][aRow] = a.z; As[aC4 + 3][aRow] = a.w;
        Bs[bC4 + 0][bN]   = b.x; Bs[bC4 + 1][bN]   = b.y;
        Bs[bC4 + 2][bN]   = b.z; Bs[bC4 + 3][bN]   = b.w;
        __syncthreads();

        #pragma unroll
        for (int k = 0; k < 16; ++k) {
            float4 ra = *reinterpret_cast<float4*>(&As[k][tr]);
            float4 rb = *reinterpret_cast<float4*>(&Bs[k][tc]);
            float fa[4] = {ra.x, ra.y, ra.z, ra.w};
            float fb[4] = {rb.x, rb.y, rb.z, rb.w};
            #pragma unroll
            for (int i = 0; i < 4; ++i)
                #pragma unroll
                for (int j = 0; j < 4; ++j)
                    acc[i][j] += fa[i] * fb[j];
        }
    }

    #pragma unroll
    for (int i = 0; i < 4; ++i) {
        int r = bm * 64 + tr + i;
        if (r >= N_NODES) break;
        #pragma unroll
        for (int j = 0; j < 4; ++j) {
            int c = bn * 64 + tc + j;
            g_h[(size_t)r * HID_DIM + c] = fmaxf(acc[i][j] + b1l[c], 0.f);
        }
    }
}

// ---------------- layer-2 projection: p = h@W2l^T, q = h@W2r^T -----------------
__global__ void __launch_bounds__(256)
k_gemm2(const float* __restrict__ W2l, const float* __restrict__ W2r) {
    __shared__ float ws[10][256];
    int tid = threadIdx.x;
    for (int i = tid; i < 5 * 256; i += 256) ws[i / 256][i % 256]     = W2l[i];
    for (int i = tid; i < 5 * 256; i += 256) ws[5 + i / 256][i % 256] = W2r[i];
    __syncthreads();

    int node = blockIdx.x * 256 + tid;
    if (node >= N_NODES) return;

    float acc[10] = {};
    const float4* hr = reinterpret_cast<const float4*>(g_h + (size_t)node * HID_DIM);
    #pragma unroll 4
    for (int k4 = 0; k4 < 64; ++k4) {
        float4 h = hr[k4];
        int k = k4 * 4;
        #pragma unroll
        for (int j = 0; j < 10; ++j)
            acc[j] += h.x * ws[j][k] + h.y * ws[j][k + 1]
                    + h.z * ws[j][k + 2] + h.w * ws[j][k + 3];
    }
    #pragma unroll
    for (int j = 0; j < 5; ++j) {
        g_p[node * 8 + j] = acc[j];
        g_q[node * 8 + j] = acc[5 + j];
    }
    #pragma unroll
    for (int j = 5; j < 8; ++j) {
        g_p[node * 8 + j] = 0.f;
        g_q[node * 8 + j] = 0.f;
    }
}

// ---------------- layer-2 aggregation + epilogue: warp per node ----------------
// lanes split into 4 groups of 8; group g handles neighbors g, g+4, ...;
// within a group, lane covers one of 8 components of p[src].
__global__ void __launch_bounds__(256)
k_agg2(const float* __restrict__ b2l, float* __restrict__ out) {
    int node = (blockIdx.x * blockDim.x + threadIdx.x) >> 5;
    int lane = threadIdx.x & 31;
    if (node >= N_NODES) return;

    int c = lane & 7;      // component 0..7
    int g = lane >> 3;     // group 0..3
    int off = g_off[node];
    int cnt = g_cnt[node];

    float acc = 0.f;
    for (int j = g; j < cnt; j += 4) {
        int s = g_nbr[off + j];
        acc += g_p[s * 8 + c];
    }
    acc += __shfl_down_sync(0xffffffffu, acc, 16);
    acc += __shfl_down_sync(0xffffffffu, acc, 8);

    if (lane < OUT_DIM) {
        float v = acc * g_inv[node] + b2l[lane] + g_q[node * 8 + lane];
        out[(size_t)node * OUT_DIM + lane] = fmaxf(v, 0.f);
    }
}

// ---------------- launch -------------------------------------------------------
extern "C" void kernel_launch(void* const* d_in, const int* in_sizes, int n_in,
                              void* d_out, int out_size) {
    const float* x   = (const float*)d_in[0];
    const int*   ei  = (const int*)d_in[1];     // int32! [src | dst]
    const float* W1l = (const float*)d_in[2];
    const float* b1l = (const float*)d_in[3];
    const float* W1r = (const float*)d_in[4];
    const float* W2l = (const float*)d_in[5];
    const float* b2l = (const float*)d_in[6];
    const float* W2r = (const float*)d_in[7];
    float* out = (float*)d_out;

    k_zero_cnt<<<(N_NODES + 255) / 256, 256>>>();
    k_hist<<<(N_EDGES + 255) / 256, 256>>>(ei);
    k_scan<<<1, 1024>>>();
    k_fill<<<(N_EDGES + 255) / 256, 256>>>(ei);
    k_agg1<<<(N_NODES * 32 + 255) / 256, 256>>>(x);
    k_gemm1<<<dim3((N_NODES + 63) / 64, HID_DIM / 64), 256>>>(x, W1l, b1l, W1r);
    k_gemm2<<<(N_NODES + 255) / 256, 256>>>(W2l, W2r);
    k_agg2<<<(N_NODES * 32 + 255) / 256, 256>>>(b2l, out);
}

// round 12
// speedup vs baseline: 1.4014x; 1.4014x over previous
#include <cuda_runtime.h>
#include <cuda_bf16.h>

#define N_NODES 50000
#define N_EDGES 800000
#define IN_DIM 128
#define HID_DIM 256
#define OUT_DIM 5
#define M_TILES 391
#define M_PAD (M_TILES * 128)   // 50048

// ---------------- scratch (device globals; no allocation allowed) -------------
__device__ int   g_cnt [N_NODES];
__device__ int   g_off [N_NODES];
__device__ int   g_cur [N_NODES];
__device__ float g_inv [N_NODES];
__device__ int   g_nbr [N_EDGES];
__device__ __nv_bfloat16 g_ahi[M_PAD * 256];   // A = [mean | x], split hi
__device__ __nv_bfloat16 g_alo[M_PAD * 256];   // A split lo
__device__ __nv_bfloat16 g_bhi[256 * 256];     // B = [W1l ; W1r] concat, hi
__device__ __nv_bfloat16 g_blo[256 * 256];     // B lo
__device__ float g_h[N_NODES * HID_DIM];       // layer-1 output (fp32)
__device__ float g_p[N_NODES * 8];
__device__ float g_q[N_NODES * 8];

// ---------------- mma.sync helper (baseline PTX, works on compute_103) ---------
__device__ __forceinline__ void mma_bf16(float* c, const unsigned* a, const unsigned* b) {
    asm volatile(
        "mma.sync.aligned.m16n8k16.row.col.f32.bf16.bf16.f32 "
        "{%0,%1,%2,%3}, {%4,%5,%6,%7}, {%8,%9}, {%0,%1,%2,%3};"
        : "+f"(c[0]), "+f"(c[1]), "+f"(c[2]), "+f"(c[3])
        : "r"(a[0]), "r"(a[1]), "r"(a[2]), "r"(a[3]), "r"(b[0]), "r"(b[1]));
}

// split fp32x4 into bf16 hi/lo, 8-byte stores
__device__ __forceinline__ void split_store4(float4 v, __nv_bfloat16* hi, __nv_bfloat16* lo) {
    __nv_bfloat16 h0 = __float2bfloat16(v.x), h1 = __float2bfloat16(v.y);
    __nv_bfloat16 h2 = __float2bfloat16(v.z), h3 = __float2bfloat16(v.w);
    __nv_bfloat16 l0 = __float2bfloat16(v.x - __bfloat162float(h0));
    __nv_bfloat16 l1 = __float2bfloat16(v.y - __bfloat162float(h1));
    __nv_bfloat16 l2 = __float2bfloat16(v.z - __bfloat162float(h2));
    __nv_bfloat16 l3 = __float2bfloat16(v.w - __bfloat162float(h3));
    ushort4 H = make_ushort4(__bfloat16_as_ushort(h0), __bfloat16_as_ushort(h1),
                             __bfloat16_as_ushort(h2), __bfloat16_as_ushort(h3));
    ushort4 L = make_ushort4(__bfloat16_as_ushort(l0), __bfloat16_as_ushort(l1),
                             __bfloat16_as_ushort(l2), __bfloat16_as_ushort(l3));
    *reinterpret_cast<ushort4*>(hi) = H;
    *reinterpret_cast<ushort4*>(lo) = L;
}

// ---------------- CSR build ----------------------------------------------------
__global__ void k_zero_cnt() {
    int i = blockIdx.x * blockDim.x + threadIdx.x;
    if (i < N_NODES) g_cnt[i] = 0;
}
__global__ void k_hist(const int* __restrict__ ei) {
    int e = blockIdx.x * blockDim.x + threadIdx.x;
    if (e >= N_EDGES) return;
    atomicAdd(&g_cnt[ei[N_EDGES + e]], 1);
}
__global__ void __launch_bounds__(1024) k_scan() {
    const int PER = (N_NODES + 1023) / 1024;
    int t = threadIdx.x, beg = t * PER, end = min(beg + PER, N_NODES);
    int s = 0;
    for (int i = beg; i < end; ++i) s += g_cnt[i];
    __shared__ int sh[1024];
    sh[t] = s;
    __syncthreads();
    for (int d = 1; d < 1024; d <<= 1) {
        int v = (t >= d) ? sh[t - d] : 0;
        __syncthreads();
        sh[t] += v;
        __syncthreads();
    }
    int run = (t == 0) ? 0 : sh[t - 1];
    for (int i = beg; i < end; ++i) {
        int c = g_cnt[i];
        g_off[i] = run; g_cur[i] = run;
        g_inv[i] = 1.0f / (float)max(c, 1);
        run += c;
    }
}
__global__ void k_fill(const int* __restrict__ ei) {
    int e = blockIdx.x * blockDim.x + threadIdx.x;
    if (e >= N_EDGES) return;
    int pos = atomicAdd(&g_cur[ei[N_EDGES + e]], 1);
    g_nbr[pos] = ei[e];
}

// ---------------- layer-1 aggregation: warp/node gather-sum -> bf16 hi/lo ------
__global__ void __launch_bounds__(256) k_agg1(const float* __restrict__ x) {
    int node = (blockIdx.x * blockDim.x + threadIdx.x) >> 5;
    int lane = threadIdx.x & 31;
    if (node >= N_NODES) return;
    int off = g_off[node], cnt = g_cnt[node];
    const float4* x4 = reinterpret_cast<const float4*>(x);
    float4 acc = make_float4(0.f, 0.f, 0.f, 0.f);
    int j = 0;
    for (; j + 2 <= cnt; j += 2) {
        int s0 = g_nbr[off + j], s1 = g_nbr[off + j + 1];
        float4 v0 = x4[(size_t)s0 * 32 + lane];
        float4 v1 = x4[(size_t)s1 * 32 + lane];
        acc.x += v0.x + v1.x; acc.y += v0.y + v1.y;
        acc.z += v0.z + v1.z; acc.w += v0.w + v1.w;
    }
    if (j < cnt) {
        float4 v = x4[(size_t)g_nbr[off + j] * 32 + lane];
        acc.x += v.x; acc.y += v.y; acc.z += v.z; acc.w += v.w;
    }
    float inv = g_inv[node];
    acc.x *= inv; acc.y *= inv; acc.z *= inv; acc.w *= inv;
    size_t o = (size_t)node * 256 + lane * 4;          // cols 0..127 = mean
    split_store4(acc, g_ahi + o, g_alo + o);
}

// x -> A cols 128..255 (bf16 hi/lo)
__global__ void __launch_bounds__(256) k_convx(const float* __restrict__ x) {
    int idx = blockIdx.x * blockDim.x + threadIdx.x;
    if (idx >= N_NODES * 32) return;
    int node = idx >> 5, lane = idx & 31;
    float4 v = reinterpret_cast<const float4*>(x)[(size_t)node * 32 + lane];
    size_t o = (size_t)node * 256 + 128 + lane * 4;
    split_store4(v, g_ahi + o, g_alo + o);
}

// weights: B[n][k] = k<128 ? W1l[n][k] : W1r[n][k-128]  (bf16 hi/lo)
__global__ void __launch_bounds__(256) k_convw(const float* __restrict__ W1l,
                                               const float* __restrict__ W1r) {
    int i = blockIdx.x * blockDim.x + threadIdx.x;
    if (i >= 256 * 256) return;
    int n = i >> 8, k = i & 255;
    float v = (k < 128) ? W1l[n * 128 + k] : W1r[n * 128 + (k - 128)];
    __nv_bfloat16 h = __float2bfloat16(v);
    g_bhi[i] = h;
    g_blo[i] = __float2bfloat16(v - __bfloat162float(h));
}

// ---------------- layer-1 GEMM via warp mma.sync (split-bf16 emulated fp32) ----
// grid (391, 2). BM=128, BN=128, BK=64, 256 thr = 8 warps (2 m x 4 n), 64x32/warp.
// SMEM row stride 72 bf16 (144 B): B fragment loads conflict-free.
#define STRIDE_B 144
#define OFF_AH 0
#define OFF_AL (OFF_AH + 128 * STRIDE_B)
#define OFF_BH (OFF_AL + 128 * STRIDE_B)
#define OFF_BL (OFF_BH + 128 * STRIDE_B)
#define GSMEM  (OFF_BL + 128 * STRIDE_B)   // 73728 B

__global__ void __launch_bounds__(256) k_gemm1_mma(const float* __restrict__ b1l) {
    extern __shared__ char smem[];
    int tid = threadIdx.x;
    int warp = tid >> 5, lane = tid & 31;
    int wm = warp >> 2;            // 0..1  (64 rows each)
    int wn = warp & 3;             // 0..3  (32 cols each)
    int g  = lane >> 2;            // 0..7
    int tg = lane & 3;             // 0..3
    int tile = blockIdx.x;         // M tile
    int bn   = blockIdx.y;         // N tile (0..1)

    const uint4* AH = reinterpret_cast<const uint4*>(g_ahi);
    const uint4* AL = reinterpret_cast<const uint4*>(g_alo);
    const uint4* BH = reinterpret_cast<const uint4*>(g_bhi);
    const uint4* BL = reinterpret_cast<const uint4*>(g_blo);

    float acc[4][4][4] = {};

    for (int kc = 0; kc < 4; ++kc) {      // K chunks of 64
        __syncthreads();
        // fill SMEM: 128 rows x 8 uint4 for each of A/B hi/lo
        #pragma unroll
        for (int i = 0; i < 4; ++i) {
            int idx = tid + i * 256;       // 0..1023
            int row = idx >> 3, c8 = idx & 7;
            size_t gA = (size_t)(tile * 128 + row) * 32 + kc * 8 + c8;
            size_t gB = (size_t)(bn * 128 + row) * 32 + kc * 8 + c8;
            char* d = smem + row * STRIDE_B + c8 * 16;
            *reinterpret_cast<uint4*>(d + OFF_AH) = AH[gA];
            *reinterpret_cast<uint4*>(d + OFF_AL) = AL[gA];
            *reinterpret_cast<uint4*>(d + OFF_BH) = BH[gB];
            *reinterpret_cast<uint4*>(d + OFF_BL) = BL[gB];
        }
        __syncthreads();

        #pragma unroll
        for (int ks = 0; ks < 4; ++ks) {   // 4 k-steps of 16
            int kb = ks * 32 + tg * 4;     // byte offset of k0 + tg*2 bf16
            unsigned ah[4][4], al[4][4];
            #pragma unroll
            for (int mt = 0; mt < 4; ++mt) {
                const char* bh_ = smem + OFF_AH + (wm * 64 + mt * 16 + g) * STRIDE_B + kb;
                const char* bl_ = smem + OFF_AL + (wm * 64 + mt * 16 + g) * STRIDE_B + kb;
                ah[mt][0] = *reinterpret_cast<const unsigned*>(bh_);
                ah[mt][1] = *reinterpret_cast<const unsigned*>(bh_ + 8 * STRIDE_B);
                ah[mt][2] = *reinterpret_cast<const unsigned*>(bh_ + 16);
                ah[mt][3] = *reinterpret_cast<const unsigned*>(bh_ + 8 * STRIDE_B + 16);
                al[mt][0] = *reinterpret_cast<const unsigned*>(bl_);
                al[mt][1] = *reinterpret_cast<const unsigned*>(bl_ + 8 * STRIDE_B);
                al[mt][2] = *reinterpret_cast<const unsigned*>(bl_ + 16);
                al[mt][3] = *reinterpret_cast<const unsigned*>(bl_ + 8 * STRIDE_B + 16);
            }
            unsigned bhf[4][2], blf[4][2];
            #pragma unroll
            for (int nt = 0; nt < 4; ++nt) {
                const char* bh_ = smem + OFF_BH + (wn * 32 + nt * 8 + g) * STRIDE_B + kb;
                const char* bl_ = smem + OFF_BL + (wn * 32 + nt * 8 + g) * STRIDE_B + kb;
                bhf[nt][0] = *reinterpret_cast<const unsigned*>(bh_);
                bhf[nt][1] = *reinterpret_cast<const unsigned*>(bh_ + 16);
                blf[nt][0] = *reinterpret_cast<const unsigned*>(bl_);
                blf[nt][1] = *reinterpret_cast<const unsigned*>(bl_ + 16);
            }
            #pragma unroll
            for (int mt = 0; mt < 4; ++mt)
                #pragma unroll
                for (int nt = 0; nt < 4; ++nt) {
                    mma_bf16(acc[mt][nt], ah[mt], bhf[nt]);   // hi*hi
                    mma_bf16(acc[mt][nt], ah[mt], blf[nt]);   // hi*lo
                    mma_bf16(acc[mt][nt], al[mt], bhf[nt]);   // lo*hi
                }
        }
    }

    // epilogue: bias + relu, write fp32 h
    #pragma unroll
    for (int mt = 0; mt < 4; ++mt) {
        int r0 = tile * 128 + wm * 64 + mt * 16 + g;
        #pragma unroll
        for (int nt = 0; nt < 4; ++nt) {
            int c = bn * 128 + wn * 32 + nt * 8 + tg * 2;
            float bx = b1l[c], by = b1l[c + 1];
            if (r0 < N_NODES) {
                float2 v = make_float2(fmaxf(acc[mt][nt][0] + bx, 0.f),
                                       fmaxf(acc[mt][nt][1] + by, 0.f));
                *reinterpret_cast<float2*>(g_h + (size_t)r0 * HID_DIM + c) = v;
            }
            if (r0 + 8 < N_NODES) {
                float2 v = make_float2(fmaxf(acc[mt][nt][2] + bx, 0.f),
                                       fmaxf(acc[mt][nt][3] + by, 0.f));
                *reinterpret_cast<float2*>(g_h + (size_t)(r0 + 8) * HID_DIM + c) = v;
            }
        }
    }
}

// ---------------- layer-2 projection: p = h@W2l^T, q = h@W2r^T -----------------
__global__ void __launch_bounds__(256)
k_gemm2(const float* __restrict__ W2l, const float* __restrict__ W2r) {
    __shared__ float ws[10][256];
    int tid = threadIdx.x;
    for (int i = tid; i < 5 * 256; i += 256) ws[i / 256][i % 256]     = W2l[i];
    for (int i = tid; i < 5 * 256; i += 256) ws[5 + i / 256][i % 256] = W2r[i];
    __syncthreads();

    int node = blockIdx.x * 256 + tid;
    if (node >= N_NODES) return;

    float acc[10] = {};
    const float4* hr = reinterpret_cast<const float4*>(g_h + (size_t)node * HID_DIM);
    #pragma unroll 4
    for (int k4 = 0; k4 < 64; ++k4) {
        float4 h = hr[k4];
        int k = k4 * 4;
        #pragma unroll
        for (int j = 0; j < 10; ++j)
            acc[j] += h.x * ws[j][k] + h.y * ws[j][k + 1]
                    + h.z * ws[j][k + 2] + h.w * ws[j][k + 3];
    }
    #pragma unroll
    for (int j = 0; j < 5; ++j) {
        g_p[node * 8 + j] = acc[j];
        g_q[node * 8 + j] = acc[5 + j];
    }
    #pragma unroll
    for (int j = 5; j < 8; ++j) {
        g_p[node * 8 + j] = 0.f;
        g_q[node * 8 + j] = 0.f;
    }
}

// ---------------- layer-2 aggregation + epilogue --------------------------------
__global__ void __launch_bounds__(256)
k_agg2(const float* __restrict__ b2l, float* __restrict__ out) {
    int node = (blockIdx.x * blockDim.x + threadIdx.x) >> 5;
    int lane = threadIdx.x & 31;
    if (node >= N_NODES) return;

    int c = lane & 7, g = lane >> 3;
    int off = g_off[node], cnt = g_cnt[node];

    float acc = 0.f;
    for (int j = g; j < cnt; j += 4)
        acc += g_p[g_nbr[off + j] * 8 + c];
    acc += __shfl_down_sync(0xffffffffu, acc, 16);
    acc += __shfl_down_sync(0xffffffffu, acc, 8);

    if (lane < OUT_DIM) {
        float v = acc * g_inv[node] + b2l[lane] + g_q[node * 8 + lane];
        out[(size_t)node * OUT_DIM + lane] = fmaxf(v, 0.f);
    }
}

// ---------------- launch -------------------------------------------------------
extern "C" void kernel_launch(void* const* d_in, const int* in_sizes, int n_in,
                              void* d_out, int out_size) {
    const float* x   = (const float*)d_in[0];
    const int*   ei  = (const int*)d_in[1];     // int32: [src | dst]
    const float* W1l = (const float*)d_in[2];
    const float* b1l = (const float*)d_in[3];
    const float* W1r = (const float*)d_in[4];
    const float* W2l = (const float*)d_in[5];
    const float* b2l = (const float*)d_in[6];
    const float* W2r = (const float*)d_in[7];
    float* out = (float*)d_out;

    cudaFuncSetAttribute(k_gemm1_mma, cudaFuncAttributeMaxDynamicSharedMemorySize,
                         GSMEM);

    k_zero_cnt<<<(N_NODES + 255) / 256, 256>>>();
    k_hist<<<(N_EDGES + 255) / 256, 256>>>(ei);
    k_scan<<<1, 1024>>>();
    k_fill<<<(N_EDGES + 255) / 256, 256>>>(ei);
    k_agg1<<<(N_NODES * 32 + 255) / 256, 256>>>(x);
    k_convx<<<(N_NODES * 32 + 255) / 256, 256>>>(x);
    k_convw<<<(256 * 256 + 255) / 256, 256>>>(W1l, W1r);
    k_gemm1_mma<<<dim3(M_TILES, 2), 256, GSMEM>>>(b1l);
    k_gemm2<<<(N_NODES + 255) / 256, 256>>>(W2l, W2r);
    k_agg2<<<(N_NODES * 32 + 255) / 256, 256>>>(b2l, out);
}